// round 2
// baseline (speedup 1.0000x reference)
#include <cuda_runtime.h>
#include <cstdint>

// Problem constants
#define FLEN 1024   // chain length
#define DDIM 1024   // bond dimension
#define NMAT 32     // physical dim (alphabet)

// Kernel config
#define NBLK 64     // persistent blocks (single wave on 148 SMs)
#define TPB  256
#define JTILES 32   // column tiles of 32 cols (128B rows)
#define ISPLIT 2    // row splits of 512 rows

// Scratch: double-buffered partial results, barrier state.
// __device__ globals (allowed; no cudaMalloc anywhere).
__device__ float    g_P[2][ISPLIT][DDIM];
__device__ unsigned g_count = 0;
__device__ unsigned g_gen   = 0;

__device__ __forceinline__ unsigned ld_acq(unsigned* p) {
    unsigned v;
    asm volatile("ld.acquire.gpu.u32 %0, [%1];" : "=r"(v) : "l"(p) : "memory");
    return v;
}

// Grid-wide barrier for exactly NBLK co-resident blocks.
// State is consistent across launches/graph replays: count returns to 0
// after every barrier, gen grows monotonically (wrap is fine).
__device__ __forceinline__ void grid_barrier() {
    __syncthreads();
    if (threadIdx.x == 0) {
        __threadfence();                       // make P stores visible
        unsigned snap = ld_acq(&g_gen);
        unsigned old  = atomicAdd(&g_count, 1u);
        if (old == NBLK - 1) {
            g_count = 0;
            __threadfence();                   // order reset before release
            atomicAdd(&g_gen, 1u);             // release
        } else {
            while (ld_acq(&g_gen) == snap) { } // acquire spin
        }
    }
    __syncthreads();
}

__global__ void __launch_bounds__(TPB, 1)
tn_chain_kernel(const int*   __restrict__ x,
                const float* __restrict__ core,
                const float* __restrict__ lb,
                const float* __restrict__ rb,
                float*       __restrict__ out)
{
    __shared__ float  sv[512];       // this block's v slice (rows i0..i0+512)
    __shared__ float4 sacc[TPB];     // per-thread accumulators for reduction
    __shared__ int    sx[FLEN];      // whole index sequence (4KB)

    const int tid   = threadIdx.x;
    const int b     = blockIdx.x;
    const int jt    = b & (JTILES - 1);   // 0..31  -> cols [jt*32, jt*32+32)
    const int is    = b >> 5;             // 0..1   -> rows [is*512, is*512+512)
    const int i0    = is * 512;
    const int c4    = tid & 7;            // which float4 within the 32-col tile
    const int owner = tid >> 3;           // 0..31 row-owner

    // Preload x once
    for (int t = tid; t < FLEN; t += TPB) sx[t] = x[t];
    __syncthreads();

    for (int t = 0; t < FLEN; ++t) {
        const int rbuf = (t + 1) & 1;
        const int wbuf = t & 1;

        // Rebuild this block's 512-entry v slice (deterministic order).
        if (t == 0) {
            sv[tid]       = lb[i0 + tid];
            sv[tid + 256] = lb[i0 + tid + 256];
        } else {
            sv[tid]       = __ldcg(&g_P[rbuf][0][i0 + tid])
                          + __ldcg(&g_P[rbuf][1][i0 + tid]);
            sv[tid + 256] = __ldcg(&g_P[rbuf][0][i0 + tid + 256])
                          + __ldcg(&g_P[rbuf][1][i0 + tid + 256]);
        }
        __syncthreads();

        const int c = sx[t];
        // float4 view of matrix c, offset to this block's column tile
        const float4* M4 = reinterpret_cast<const float4*>(
                               core + (size_t)c * DDIM * DDIM)
                           + (size_t)jt * 8 + c4;

        float4 acc = make_float4(0.f, 0.f, 0.f, 0.f);
        #pragma unroll
        for (int k = 0; k < 16; ++k) {
            const int iloc = owner + k * 32;
            const float vv = sv[iloc];
            const float4 m = M4[(size_t)(i0 + iloc) * 256];  // row stride 4KB
            acc.x += vv * m.x;
            acc.y += vv * m.y;
            acc.z += vv * m.z;
            acc.w += vv * m.w;
        }
        sacc[tid] = acc;
        __syncthreads();

        // 32 threads reduce the 32 row-owners for their column (fixed order).
        if (tid < 32) {
            const int cc4 = tid >> 2, comp = tid & 3;
            const float* sa = reinterpret_cast<const float*>(sacc);
            float s = 0.f;
            #pragma unroll
            for (int o = 0; o < 32; ++o)
                s += sa[o * 32 + cc4 * 4 + comp];   // conflict-free: addr = o*32 + tid
            __stcg(&g_P[wbuf][is][jt * 32 + tid], s);
        }

        grid_barrier();
    }

    // Final partials live in buffer (FLEN-1)&1 == 1. Block 0 does the dot.
    if (b == 0) {
        float part = 0.f;
        for (int j = tid; j < DDIM; j += TPB)
            part += (__ldcg(&g_P[1][0][j]) + __ldcg(&g_P[1][1][j])) * rb[j];
        __shared__ float sred[TPB];
        sred[tid] = part;
        __syncthreads();
        #pragma unroll
        for (int s = TPB / 2; s > 0; s >>= 1) {
            if (tid < s) sred[tid] += sred[tid + s];
            __syncthreads();
        }
        if (tid == 0) out[0] = sred[0];
    }
}

extern "C" void kernel_launch(void* const* d_in, const int* in_sizes, int n_in,
                              void* d_out, int out_size) {
    const int*   x    = (const int*)  d_in[0];  // int32[1024]
    const float* core = (const float*)d_in[1];  // f32[32,1024,1024]
    const float* lb   = (const float*)d_in[2];  // f32[1024]
    const float* rb   = (const float*)d_in[3];  // f32[1024]
    float*       out  = (float*)d_out;

    tn_chain_kernel<<<NBLK, TPB>>>(x, core, lb, rb, out);
}

// round 3
// speedup vs baseline: 2.0930x; 2.0930x over previous
#include <cuda_runtime.h>
#include <cstdint>

#define FLEN 1024   // chain length
#define DDIM 1024   // bond dimension
#define HALF 512    // steps per direction
#define NGRP 64     // blocks per direction
#define NBLK (2*NGRP)
#define TPB  256

// Double-buffered chain vectors + per-group barrier state (__device__ globals:
// no cudaMalloc anywhere). State is replay-consistent: counters return to 0,
// generations grow monotonically (wrap handled by signed compare).
__device__ float    g_V[2][DDIM];   // forward vector
__device__ float    g_W[2][DDIM];   // backward vector
__device__ unsigned g_cnt_f = 0, g_gen_f = 0;
__device__ unsigned g_cnt_b = 0, g_gen_b = 0;

__device__ __forceinline__ unsigned ld_acq(const unsigned* p) {
    unsigned v;
    asm volatile("ld.acquire.gpu.u32 %0, [%1];" : "=r"(v) : "l"(p) : "memory");
    return v;
}

__global__ void __launch_bounds__(TPB, 1)
tn_bidir_kernel(const int*   __restrict__ x,
                const float* __restrict__ core,
                const float* __restrict__ lb,
                const float* __restrict__ rb,
                float*       __restrict__ out)
{
    __shared__ float sv[DDIM];        // current chain vector (4KB)
    __shared__ float swp[8][4][4];    // fwd cross-warp reduce scratch
    __shared__ int   sx[HALF];        // this direction's index slice
    __shared__ float sred[8];

    const int tid  = threadIdx.x;
    const int b    = blockIdx.x;
    const int lane = tid & 31;
    const int wid  = tid >> 5;
    const bool fwd = (b < NGRP);

    unsigned* cnt = fwd ? &g_cnt_f : &g_cnt_b;
    unsigned* gen = fwd ? &g_gen_f : &g_gen_b;

    // Generation snapshots (safe: gen can't advance until every group member
    // arrives, and we haven't arrived yet).
    const unsigned snap = ld_acq(gen);
    unsigned snap_b0 = 0;
    if (b == 0) snap_b0 = ld_acq(&g_gen_b);

    // Load this direction's index slice (backward consumes x in reverse).
    if (fwd) { for (int t = tid; t < HALF; t += TPB) sx[t] = x[t]; }
    else     { for (int t = tid; t < HALF; t += TPB) sx[t] = x[FLEN - 1 - t]; }
    __syncthreads();

    if (fwd) {
        // ---------- forward: v_j <- sum_i v_i * M[i][j], block owns 16 cols ----------
        const int c0 = b * 16;
        const int j4 = tid & 3;       // float4 within the 16-col tile
        const int g  = tid >> 2;      // row class: rows g + 64k

        float4 m[16];
        {   // prefetch step 0
            const float4* M4 = reinterpret_cast<const float4*>(
                                   core + ((size_t)sx[0] << 20)) + (c0 >> 2) + j4;
            #pragma unroll
            for (int k = 0; k < 16; ++k) m[k] = __ldcg(&M4[(size_t)(g + 64*k) * 256]);
        }

        for (int t = 0; t < HALF; ++t) {
            if (t > 0) {
                if (wid == 0) {
                    const unsigned tgt = snap + (unsigned)t;
                    while ((int)(ld_acq(gen) - tgt) < 0) { }
                }
                __syncthreads();
            }
            // load chain vector into smem (1 float4/thread)
            {
                float4 vv = (t == 0)
                    ? reinterpret_cast<const float4*>(lb)[tid]
                    : __ldcg(&reinterpret_cast<const float4*>(g_V[(t + 1) & 1])[tid]);
                reinterpret_cast<float4*>(sv)[tid] = vv;
            }
            __syncthreads();

            float ax = 0.f, ay = 0.f, az = 0.f, aw = 0.f;
            #pragma unroll
            for (int k = 0; k < 16; ++k) {
                const float vs = sv[g + 64*k];
                ax += vs * m[k].x; ay += vs * m[k].y;
                az += vs * m[k].z; aw += vs * m[k].w;
            }

            // prefetch next step's tile ASAP (independent of v; overlaps
            // reduce + barrier + spin)
            if (t + 1 < HALF) {
                const float4* M4 = reinterpret_cast<const float4*>(
                                       core + ((size_t)sx[t+1] << 20)) + (c0 >> 2) + j4;
                #pragma unroll
                for (int k = 0; k < 16; ++k) m[k] = __ldcg(&M4[(size_t)(g + 64*k) * 256]);
            }

            // reduce over g within warp (lane bits 2..4)
            #pragma unroll
            for (int off = 4; off < 32; off <<= 1) {
                ax += __shfl_xor_sync(0xffffffffu, ax, off);
                ay += __shfl_xor_sync(0xffffffffu, ay, off);
                az += __shfl_xor_sync(0xffffffffu, az, off);
                aw += __shfl_xor_sync(0xffffffffu, aw, off);
            }
            if (lane < 4) {
                swp[wid][lane][0] = ax; swp[wid][lane][1] = ay;
                swp[wid][lane][2] = az; swp[wid][lane][3] = aw;
            }
            __syncthreads();
            if (tid < 16) {   // cross-warp reduce, write owned 16 outputs
                float s = 0.f;
                #pragma unroll
                for (int w = 0; w < 8; ++w) s += swp[w][tid >> 2][tid & 3];
                __stcg(&g_V[t & 1][c0 + tid], s);
            }
            __syncthreads();
            if (tid == 0) {
                __threadfence();
                const unsigned old = atomicAdd(cnt, 1u);
                if (old == NGRP - 1) { *cnt = 0; __threadfence(); atomicAdd(gen, 1u); }
            }
        }
    } else {
        // ---------- backward: w_i <- sum_j M[i][j] * w_j, block owns 16 rows ----------
        const int r0    = (b - NGRP) * 16;
        const int chunk = tid & 15;   // float4 chunk within a row
        const int row   = r0 + (tid >> 4);

        float4 m[16];
        {   // prefetch step 0
            const float4* M4 = reinterpret_cast<const float4*>(
                                   core + ((size_t)sx[0] << 20))
                               + (size_t)row * 256 + chunk;
            #pragma unroll
            for (int k = 0; k < 16; ++k) m[k] = __ldcg(&M4[16 * k]);
        }

        for (int t = 0; t < HALF; ++t) {
            if (t > 0) {
                if (wid == 0) {
                    const unsigned tgt = snap + (unsigned)t;
                    while ((int)(ld_acq(gen) - tgt) < 0) { }
                }
                __syncthreads();
            }
            {
                float4 vv = (t == 0)
                    ? reinterpret_cast<const float4*>(rb)[tid]
                    : __ldcg(&reinterpret_cast<const float4*>(g_W[(t + 1) & 1])[tid]);
                reinterpret_cast<float4*>(sv)[tid] = vv;
            }
            __syncthreads();

            float a0 = 0.f, a1 = 0.f, a2 = 0.f, a3 = 0.f;
            const float4* sw4 = reinterpret_cast<const float4*>(sv);
            #pragma unroll
            for (int k = 0; k < 16; ++k) {
                const float4 wv = sw4[chunk + 16*k];
                a0 += m[k].x * wv.x; a1 += m[k].y * wv.y;
                a2 += m[k].z * wv.z; a3 += m[k].w * wv.w;
            }
            float acc = (a0 + a1) + (a2 + a3);

            if (t + 1 < HALF) {
                const float4* M4 = reinterpret_cast<const float4*>(
                                       core + ((size_t)sx[t+1] << 20))
                                   + (size_t)row * 256 + chunk;
                #pragma unroll
                for (int k = 0; k < 16; ++k) m[k] = __ldcg(&M4[16 * k]);
            }

            // reduce over chunk within half-warp (lane bits 0..3)
            #pragma unroll
            for (int off = 1; off < 16; off <<= 1)
                acc += __shfl_xor_sync(0xffffffffu, acc, off);
            if (chunk == 0) __stcg(&g_W[t & 1][row], acc);

            __syncthreads();
            if (tid == 0) {
                __threadfence();
                const unsigned old = atomicAdd(cnt, 1u);
                if (old == NGRP - 1) { *cnt = 0; __threadfence(); atomicAdd(gen, 1u); }
            }
        }
    }

    // ---------- final combine: block 0 waits for both chains, dots v·w ----------
    if (b == 0) {
        if (wid == 0) {
            const unsigned tf = snap    + (unsigned)HALF;
            const unsigned tb = snap_b0 + (unsigned)HALF;
            while ((int)(ld_acq(&g_gen_f) - tf) < 0) { }
            while ((int)(ld_acq(&g_gen_b) - tb) < 0) { }
        }
        __syncthreads();

        float part = 0.f;
        #pragma unroll
        for (int j = tid; j < DDIM; j += TPB)
            part += __ldcg(&g_V[1][j]) * __ldcg(&g_W[1][j]);
        #pragma unroll
        for (int off = 16; off > 0; off >>= 1)
            part += __shfl_xor_sync(0xffffffffu, part, off);
        if (lane == 0) sred[wid] = part;
        __syncthreads();
        if (tid == 0) {
            float s = 0.f;
            #pragma unroll
            for (int w = 0; w < 8; ++w) s += sred[w];
            out[0] = s;
        }
    }
}

extern "C" void kernel_launch(void* const* d_in, const int* in_sizes, int n_in,
                              void* d_out, int out_size) {
    const int*   x    = (const int*)  d_in[0];  // int32[1024]
    const float* core = (const float*)d_in[1];  // f32[32,1024,1024]
    const float* lb   = (const float*)d_in[2];  // f32[1024]
    const float* rb   = (const float*)d_in[3];  // f32[1024]
    float*       out  = (float*)d_out;

    tn_bidir_kernel<<<NBLK, TPB>>>(x, core, lb, rb, out);
}